// round 6
// baseline (speedup 1.0000x reference)
#include <cuda_runtime.h>
#include <math.h>

// Problem sizes (fixed by the reference)
#define BB 256
#define DD 512
#define HH 512

#define NPROJ   96          // producer blocks (bids 0..95 -> wave-1 resident, no deadlock)
#define GROUPS  8           // batch groups of 32 rows
#define NT      48          // n-tiles (64 cols) per group
#define NTILES  (GROUPS*NT) // 384 proj tiles of 32x64

// Scratch: projections q,k,v,i,f,o  -> 6 * 256 * 512 * 4B = 3 MB
__device__ float g_proj[6][BB][HH];
__device__ int   g_done[GROUPS];   // per-group completed-tile counters

struct KArgs {
    const float* x;        // [B, D]
    const float* Cprev;    // [B, H, H]
    const float* W[6];     // each [H, D]
    const float* bias[3];  // b_i, b_f, b_o
    float* out_h;          // [B, H]
    float* out_C;          // [B, H, H]
};

__global__ void init_flags() {
    if (threadIdx.x < GROUPS) g_done[threadIdx.x] = 0;
}

// ---------------- producer: one 32x64 proj tile ----------------
// 128 threads, BK=16, double-buffered smem, 4x4 microtile (proven R5 pipeline).
__device__ __forceinline__ void do_proj_tile(const KArgs& a, int tile,
                                             float As[2][16][32], float Bs[2][16][64]) {
    const int BK = 16;
    const int g      = tile / NT;          // batch group (32 rows)
    const int n_tile = tile % NT;
    const int row0   = g * 32;
    const int which  = (n_tile * 64) / HH;
    const int h0     = (n_tile * 64) % HH;

    const float* __restrict__ W = a.W[which];
    const float* __restrict__ x = a.x;

    const int tid = threadIdx.x;
    // A loader: 128 float4s (32 rows x 4) -> 1 per thread
    const int arow = tid >> 2;           // 0..31
    const int akq  = (tid & 3) * 4;      // 0,4,8,12
    // B loader: 256 float4s (64 rows x 4) -> 2 per thread (idx, idx+128)
    const int brow0 = tid >> 2;          // 0..31
    const int bkq0  = (tid & 3) * 4;
    const int brow1 = (tid + 128) >> 2;  // 32..63
    const int bkq1  = bkq0;
    // Compute mapping: 8x16 thread grid of 4x4 micro-tiles
    const int tr = tid >> 4;             // 0..7  -> rows tr*4..+3
    const int tc = tid & 15;             // 0..15 -> cols tc*4..+3

    float acc[4][4];
#pragma unroll
    for (int i = 0; i < 4; i++)
#pragma unroll
        for (int j = 0; j < 4; j++) acc[i][j] = 0.0f;

    const float* gA  = x + (size_t)(row0 + arow) * DD + akq;
    const float* gB0 = W + (size_t)(h0 + brow0) * DD + bkq0;
    const float* gB1 = W + (size_t)(h0 + brow1) * DD + bkq1;

    // Prologue: tile 0 -> smem buf 0
    float4 ra  = *(const float4*)gA;
    float4 rb0 = *(const float4*)gB0;
    float4 rb1 = *(const float4*)gB1;
    As[0][akq + 0][arow] = ra.x;  As[0][akq + 1][arow] = ra.y;
    As[0][akq + 2][arow] = ra.z;  As[0][akq + 3][arow] = ra.w;
    Bs[0][bkq0 + 0][brow0] = rb0.x; Bs[0][bkq0 + 1][brow0] = rb0.y;
    Bs[0][bkq0 + 2][brow0] = rb0.z; Bs[0][bkq0 + 3][brow0] = rb0.w;
    Bs[0][bkq1 + 0][brow1] = rb1.x; Bs[0][bkq1 + 1][brow1] = rb1.y;
    Bs[0][bkq1 + 2][brow1] = rb1.z; Bs[0][bkq1 + 3][brow1] = rb1.w;
    __syncthreads();

    const int T = DD / BK;  // 32 k-tiles
#pragma unroll 1
    for (int t = 0; t < T; t++) {
        const int cur = t & 1;
        const int nxt = cur ^ 1;

        if (t + 1 < T) {
            ra  = *(const float4*)(gA  + (t + 1) * BK);
            rb0 = *(const float4*)(gB0 + (t + 1) * BK);
            rb1 = *(const float4*)(gB1 + (t + 1) * BK);
        }

#pragma unroll
        for (int kk = 0; kk < BK; kk++) {
            const float4 av = *(const float4*)&As[cur][kk][tr * 4];
            const float4 bv = *(const float4*)&Bs[cur][kk][tc * 4];
            const float ar[4] = {av.x, av.y, av.z, av.w};
            const float br[4] = {bv.x, bv.y, bv.z, bv.w};
#pragma unroll
            for (int i = 0; i < 4; i++)
#pragma unroll
                for (int j = 0; j < 4; j++) acc[i][j] = fmaf(ar[i], br[j], acc[i][j]);
        }

        if (t + 1 < T) {
            As[nxt][akq + 0][arow] = ra.x;  As[nxt][akq + 1][arow] = ra.y;
            As[nxt][akq + 2][arow] = ra.z;  As[nxt][akq + 3][arow] = ra.w;
            Bs[nxt][bkq0 + 0][brow0] = rb0.x; Bs[nxt][bkq0 + 1][brow0] = rb0.y;
            Bs[nxt][bkq0 + 2][brow0] = rb0.z; Bs[nxt][bkq0 + 3][brow0] = rb0.w;
            Bs[nxt][bkq1 + 0][brow1] = rb1.x; Bs[nxt][bkq1 + 1][brow1] = rb1.y;
            Bs[nxt][bkq1 + 2][brow1] = rb1.z; Bs[nxt][bkq1 + 3][brow1] = rb1.w;
        }
        __syncthreads();
    }

    // Epilogue: bias + sigmoid for i/f/o
    const bool gate = (which >= 3);
    const float* __restrict__ bias = gate ? a.bias[which - 3] : nullptr;
#pragma unroll
    for (int i = 0; i < 4; i++) {
        const int r = row0 + tr * 4 + i;
#pragma unroll
        for (int j = 0; j < 4; j++) {
            const int h = h0 + tc * 4 + j;
            float v = acc[i][j];
            if (gate) {
                v += bias[h];
                v = 1.0f / (1.0f + __expf(-v));
            }
            g_proj[which][r][h] = v;
        }
    }

    // Publish: all global writes -> fence -> counter (threadFenceReduction pattern)
    __threadfence();
    __syncthreads();
    if (threadIdx.x == 0) atomicAdd(&g_done[g], 1);
    __syncthreads();   // keep smem buffers safe before next tile reuses them
}

// ---------------- fused kernel: producer blocks + consumer blocks ----------------
__global__ __launch_bounds__(128) void fused_kernel(KArgs a) {
    __shared__ float smem[2 * 16 * 32 + 2 * 16 * 64 + 1024];  // union: proj tiles / sv+sq

    if (blockIdx.x < NPROJ) {
        // -------- producer role --------
        float (*As)[16][32] = (float (*)[16][32])smem;
        float (*Bs)[16][64] = (float (*)[16][64])(smem + 2 * 16 * 32);
#pragma unroll 1
        for (int t = blockIdx.x; t < NTILES; t += NPROJ)
            do_proj_tile(a, t, As, Bs);
        return;
    }

    // -------- consumer role: 4 rows of C per block --------
    const int u   = blockIdx.x - NPROJ;
    const int b   = u >> 7;              // 128 blocks per batch element
    const int i0  = (u & 127) << 2;      // 4 rows
    const int tid = threadIdx.x;
    const int g   = b >> 5;              // batch group (32 rows of b)

    // Wait for this group's projections
    if (tid == 0) {
        while (*(volatile int*)&g_done[g] < NT) __nanosleep(128);
    }
    __syncthreads();
    __threadfence();   // acquire: order g_proj reads after flag observation

    float* sv = smem;
    float* sq = smem + 512;
    ((float4*)sv)[tid] = ((const float4*)&g_proj[2][b][0])[tid];  // v[b,:]
    ((float4*)sq)[tid] = ((const float4*)&g_proj[0][b][0])[tid];  // q[b,:]
    __syncthreads();

    const int warp = tid >> 5;
    const int lane = tid & 31;
    const int i    = i0 + warp;

    const float f_bi = g_proj[4][b][i];
    const float ik   = g_proj[3][b][i] * g_proj[1][b][i];
    const float o_bi = g_proj[5][b][i];

    const size_t rowoff = ((size_t)b * HH + i) * HH;
    const float4* __restrict__ Cp = (const float4*)(a.Cprev + rowoff);
    float4* __restrict__ Ct       = (float4*)(a.out_C + rowoff);
    const float4* __restrict__ v4 = (const float4*)sv;
    const float4* __restrict__ q4 = (const float4*)sq;

    float acc = 0.0f;
#pragma unroll
    for (int it = 0; it < 4; it++) {
        const int j4 = it * 32 + lane;    // 128 float4s per row
        float4 c = Cp[j4];
        const float4 vv = v4[j4];
        const float4 qq = q4[j4];
        c.x = fmaf(f_bi, c.x, ik * vv.x);
        c.y = fmaf(f_bi, c.y, ik * vv.y);
        c.z = fmaf(f_bi, c.z, ik * vv.z);
        c.w = fmaf(f_bi, c.w, ik * vv.w);
        Ct[j4] = c;
        acc += c.x * qq.x + c.y * qq.y + c.z * qq.z + c.w * qq.w;
    }

#pragma unroll
    for (int off = 16; off > 0; off >>= 1)
        acc += __shfl_xor_sync(0xFFFFFFFFu, acc, off);

    if (lane == 0) a.out_h[(size_t)b * HH + i] = o_bi * tanhf(acc);
}

extern "C" void kernel_launch(void* const* d_in, const int* in_sizes, int n_in,
                              void* d_out, int out_size) {
    // Inputs: 0:x 1:h_prev(unused) 2:C_prev 3:W_q 4:W_k 5:W_v 6:W_i 7:W_f 8:W_o 9:b_i 10:b_f 11:b_o
    KArgs a;
    a.x     = (const float*)d_in[0];
    a.Cprev = (const float*)d_in[2];
    a.W[0] = (const float*)d_in[3];
    a.W[1] = (const float*)d_in[4];
    a.W[2] = (const float*)d_in[5];
    a.W[3] = (const float*)d_in[6];
    a.W[4] = (const float*)d_in[7];
    a.W[5] = (const float*)d_in[8];
    a.bias[0] = (const float*)d_in[9];
    a.bias[1] = (const float*)d_in[10];
    a.bias[2] = (const float*)d_in[11];

    float* out = (float*)d_out;
    a.out_h = out;                       // [B, H]
    a.out_C = out + (size_t)BB * HH;     // [B, H, H]

    init_flags<<<1, 32>>>();
    const int n_update = BB * (HH / 4);          // 32768 consumer blocks
    fused_kernel<<<NPROJ + n_update, 128>>>(a);  // producers at low bids: wave-1 resident
}

// round 8
// speedup vs baseline: 1.3677x; 1.3677x over previous
#include <cuda_runtime.h>
#include <math.h>

// Problem sizes (fixed by the reference)
#define BB 256
#define DD 512
#define HH 512

// Scratch: projections q,k,v,i,f,o  -> 6 * 256 * 512 * 4B = 3 MB
__device__ float g_proj[6][BB][HH];

struct GemmArgs {
    const float* x;        // [B, D] row-major
    const float* W[6];     // each [H, D] row-major (x @ W.T => dot of rows)
    const float* bias[3];  // b_i, b_f, b_o (for which = 3,4,5)
};

// Fused 6-way projection GEMM: M=256, N=3072 (6*512), K=512.
// 32x64 tiles, 384 blocks of 128 threads (fine-grained for wave balance),
// BK=16 double-buffered smem, 4x4 microtile, one __syncthreads per k-tile.
__global__ __launch_bounds__(128) void proj_kernel(GemmArgs a) {
    const int BK = 16;
    __shared__ float As[2][BK][32];   // As[buf][k][m]
    __shared__ float Bs[2][BK][64];   // Bs[buf][k][n]

    const int n_tile = blockIdx.x;           // 0..47
    const int m_tile = blockIdx.y;           // 0..7
    const int which  = (n_tile * 64) / HH;   // which weight matrix
    const int h0     = (n_tile * 64) % HH;   // column offset within that matrix
    const int row0   = m_tile * 32;

    const float* __restrict__ W = a.W[which];
    const float* __restrict__ x = a.x;

    const int tid = threadIdx.x;
    // A loader: 128 float4s (32 rows x 4 along K) -> 1 per thread
    const int arow = tid >> 2;           // 0..31
    const int akq  = (tid & 3) * 4;      // 0,4,8,12
    // B loader: 256 float4s (64 rows x 4) -> 2 per thread
    const int brow0 = tid >> 2;          // 0..31
    const int bkq   = (tid & 3) * 4;
    const int brow1 = brow0 + 32;        // 32..63
    // Compute mapping: 8x16 thread grid of 4x4 micro-tiles
    const int tr = tid >> 4;             // 0..7  -> rows tr*4..+3
    const int tc = tid & 15;             // 0..15 -> cols tc*4..+3

    float acc[4][4];
#pragma unroll
    for (int i = 0; i < 4; i++)
#pragma unroll
        for (int j = 0; j < 4; j++) acc[i][j] = 0.0f;

    const float* gA  = x + (size_t)(row0 + arow) * DD + akq;
    const float* gB0 = W + (size_t)(h0 + brow0) * DD + bkq;
    const float* gB1 = W + (size_t)(h0 + brow1) * DD + bkq;

    // Prologue: k-tile 0 -> smem buf 0
    float4 ra  = *(const float4*)gA;
    float4 rb0 = *(const float4*)gB0;
    float4 rb1 = *(const float4*)gB1;
    As[0][akq + 0][arow] = ra.x;  As[0][akq + 1][arow] = ra.y;
    As[0][akq + 2][arow] = ra.z;  As[0][akq + 3][arow] = ra.w;
    Bs[0][bkq + 0][brow0] = rb0.x; Bs[0][bkq + 1][brow0] = rb0.y;
    Bs[0][bkq + 2][brow0] = rb0.z; Bs[0][bkq + 3][brow0] = rb0.w;
    Bs[0][bkq + 0][brow1] = rb1.x; Bs[0][bkq + 1][brow1] = rb1.y;
    Bs[0][bkq + 2][brow1] = rb1.z; Bs[0][bkq + 3][brow1] = rb1.w;
    __syncthreads();

    const int T = DD / BK;  // 32 k-tiles
#pragma unroll 1
    for (int t = 0; t < T; t++) {
        const int cur = t & 1;
        const int nxt = cur ^ 1;

        // Prefetch next k-tile into registers (latency under compute)
        if (t + 1 < T) {
            ra  = *(const float4*)(gA  + (t + 1) * BK);
            rb0 = *(const float4*)(gB0 + (t + 1) * BK);
            rb1 = *(const float4*)(gB1 + (t + 1) * BK);
        }

#pragma unroll
        for (int kk = 0; kk < BK; kk++) {
            const float4 av = *(const float4*)&As[cur][kk][tr * 4];
            const float4 bv = *(const float4*)&Bs[cur][kk][tc * 4];
            const float ar[4] = {av.x, av.y, av.z, av.w};
            const float br[4] = {bv.x, bv.y, bv.z, bv.w};
#pragma unroll
            for (int i = 0; i < 4; i++)
#pragma unroll
                for (int j = 0; j < 4; j++) acc[i][j] = fmaf(ar[i], br[j], acc[i][j]);
        }

        if (t + 1 < T) {
            As[nxt][akq + 0][arow] = ra.x;  As[nxt][akq + 1][arow] = ra.y;
            As[nxt][akq + 2][arow] = ra.z;  As[nxt][akq + 3][arow] = ra.w;
            Bs[nxt][bkq + 0][brow0] = rb0.x; Bs[nxt][bkq + 1][brow0] = rb0.y;
            Bs[nxt][bkq + 2][brow0] = rb0.z; Bs[nxt][bkq + 3][brow0] = rb0.w;
            Bs[nxt][bkq + 0][brow1] = rb1.x; Bs[nxt][bkq + 1][brow1] = rb1.y;
            Bs[nxt][bkq + 2][brow1] = rb1.z; Bs[nxt][bkq + 3][brow1] = rb1.w;
        }
        __syncthreads();
    }

    // Epilogue: bias + sigmoid for i/f/o, write to scratch
    const bool gate = (which >= 3);
    const float* __restrict__ bias = gate ? a.bias[which - 3] : nullptr;
#pragma unroll
    for (int i = 0; i < 4; i++) {
        const int r = row0 + tr * 4 + i;
#pragma unroll
        for (int j = 0; j < 4; j++) {
            const int h = h0 + tc * 4 + j;
            float v = acc[i][j];
            if (gate) {
                v += bias[h];
                v = 1.0f / (1.0f + __expf(-v));
            }
            g_proj[which][r][h] = v;
        }
    }
}

// Fused state update + readout. One warp per (b, i) row; MLP=4 batched loads.
// With PDL: C_prev loads (proj-independent) issue BEFORE the grid dependency
// sync; g_proj reads happen after. Safe if PDL doesn't engage (degrades to serial).
__global__ __launch_bounds__(512) void update_kernel(const float* __restrict__ Cprev,
                                                     float* __restrict__ out_h,
                                                     float* __restrict__ out_C) {
    __shared__ float sv[HH];
    __shared__ float sq[HH];

    const int b   = blockIdx.y;
    const int i0  = blockIdx.x * 16;
    const int tid = threadIdx.x;
    const int warp = tid >> 5;
    const int lane = tid & 31;
    const int i    = i0 + warp;

    const size_t rowoff = ((size_t)b * HH + i) * HH;
    const float4* __restrict__ Cp = (const float4*)(Cprev + rowoff);
    float4* __restrict__ Ct       = (float4*)(out_C + rowoff);

    // Front-batched C_prev loads (MLP=4), independent of proj results
    float4 c[4];
#pragma unroll
    for (int it = 0; it < 4; it++) c[it] = Cp[it * 32 + lane];

    // Wait for proj_kernel results before touching g_proj
    cudaGridDependencySynchronize();

    sv[tid] = g_proj[2][b][tid];
    sq[tid] = g_proj[0][b][tid];
    __syncthreads();

    const float f_bi = g_proj[4][b][i];
    const float ik   = g_proj[3][b][i] * g_proj[1][b][i];
    const float o_bi = g_proj[5][b][i];

    const float4* __restrict__ v4 = (const float4*)sv;
    const float4* __restrict__ q4 = (const float4*)sq;

    float acc = 0.0f;
#pragma unroll
    for (int it = 0; it < 4; it++) {
        const int j4 = it * 32 + lane;    // 128 float4s per row
        const float4 vv = v4[j4];
        const float4 qq = q4[j4];
        float4 cc = c[it];
        cc.x = fmaf(f_bi, cc.x, ik * vv.x);
        cc.y = fmaf(f_bi, cc.y, ik * vv.y);
        cc.z = fmaf(f_bi, cc.z, ik * vv.z);
        cc.w = fmaf(f_bi, cc.w, ik * vv.w);
        Ct[j4] = cc;
        acc += cc.x * qq.x + cc.y * qq.y + cc.z * qq.z + cc.w * qq.w;
    }

    // Warp reduction for the dot product
#pragma unroll
    for (int off = 16; off > 0; off >>= 1)
        acc += __shfl_xor_sync(0xFFFFFFFFu, acc, off);

    if (lane == 0) out_h[(size_t)b * HH + i] = o_bi * tanhf(acc);
}

extern "C" void kernel_launch(void* const* d_in, const int* in_sizes, int n_in,
                              void* d_out, int out_size) {
    // Inputs: 0:x 1:h_prev(unused) 2:C_prev 3:W_q 4:W_k 5:W_v 6:W_i 7:W_f 8:W_o 9:b_i 10:b_f 11:b_o
    const float* x     = (const float*)d_in[0];
    const float* Cprev = (const float*)d_in[2];

    GemmArgs a;
    a.x = x;
    a.W[0] = (const float*)d_in[3];
    a.W[1] = (const float*)d_in[4];
    a.W[2] = (const float*)d_in[5];
    a.W[3] = (const float*)d_in[6];
    a.W[4] = (const float*)d_in[7];
    a.W[5] = (const float*)d_in[8];
    a.bias[0] = (const float*)d_in[9];
    a.bias[1] = (const float*)d_in[10];
    a.bias[2] = (const float*)d_in[11];

    float* out = (float*)d_out;
    float* out_h = out;                       // [B, H]
    float* out_C = out + (size_t)BB * HH;     // [B, H, H]

    dim3 gGemm(48, 8);            // 384 blocks: 32x64 tiles
    proj_kernel<<<gGemm, 128>>>(a);

    // Update with PDL: may begin (and prefetch C_prev) while proj drains.
    cudaLaunchConfig_t cfg = {};
    cfg.gridDim  = dim3(HH / 16, BB);   // (32, 256)
    cfg.blockDim = dim3(512);
    cudaLaunchAttribute attrs[1];
    attrs[0].id = cudaLaunchAttributeProgrammaticStreamSerialization;
    attrs[0].val.programmaticStreamSerializationAllowed = 1;
    cfg.attrs = attrs;
    cfg.numAttrs = 1;
    cudaLaunchKernelEx(&cfg, update_kernel, Cprev, out_h, out_C);
}

// round 10
// speedup vs baseline: 1.6004x; 1.1701x over previous
#include <cuda_runtime.h>
#include <math.h>

// Problem sizes (fixed by the reference)
#define BB 256
#define DD 512
#define HH 512

// Scratch: projections q,k,v,i,f,o  -> 6 * 256 * 512 * 4B = 3 MB
__device__ float g_proj[6][BB][HH];

struct GemmArgs {
    const float* x;        // [B, D] row-major
    const float* W[6];     // each [H, D] row-major (x @ W.T => dot of rows)
    const float* bias[3];  // b_i, b_f, b_o (for which = 3,4,5)
};

// Fused 6-way projection GEMM: M=256, N=3072 (6*512), K=512.
// 32x64 tiles, 384 blocks x 256 threads (one packed wave, ~5 warps/SMSP),
// 2x4 microtile, BK=16 double-buffered smem, one __syncthreads per k-tile.
__global__ __launch_bounds__(256) void proj_kernel(GemmArgs a) {
    const int BK = 16;
    __shared__ float As[2][BK][32];   // As[buf][k][m]
    __shared__ float Bs[2][BK][64];   // Bs[buf][k][n]

    const int n_tile = blockIdx.x;           // 0..47
    const int m_tile = blockIdx.y;           // 0..7
    const int which  = (n_tile * 64) / HH;   // which weight matrix
    const int h0     = (n_tile * 64) % HH;   // column offset within that matrix
    const int row0   = m_tile * 32;

    const float* __restrict__ W = a.W[which];
    const float* __restrict__ x = a.x;

    const int tid = threadIdx.x;
    // A loader: 128 float4s (32 rows x 4 along K) -> threads 0..127, 1 each
    const bool aload = (tid < 128);
    const int arow = tid >> 2;           // 0..31 (valid when aload)
    const int akq  = (tid & 3) * 4;      // 0,4,8,12
    // B loader: 256 float4s (64 rows x 4 along K) -> all 256 threads, 1 each
    const int brow = tid >> 2;           // 0..63
    const int bkq  = (tid & 3) * 4;      // 0,4,8,12
    // Compute mapping: 16x16 thread grid of 2x4 micro-tiles
    const int tr = tid >> 4;             // 0..15 -> rows tr*2..+1
    const int tc = tid & 15;             // 0..15 -> cols tc*4..+3

    float acc[2][4];
#pragma unroll
    for (int i = 0; i < 2; i++)
#pragma unroll
        for (int j = 0; j < 4; j++) acc[i][j] = 0.0f;

    const float* gA = x + (size_t)(row0 + arow) * DD + akq;   // valid if aload
    const float* gB = W + (size_t)(h0 + brow) * DD + bkq;

    // Prologue: k-tile 0 -> smem buf 0
    float4 ra = make_float4(0.f, 0.f, 0.f, 0.f);
    if (aload) ra = *(const float4*)gA;
    float4 rb = *(const float4*)gB;
    if (aload) {
        As[0][akq + 0][arow] = ra.x; As[0][akq + 1][arow] = ra.y;
        As[0][akq + 2][arow] = ra.z; As[0][akq + 3][arow] = ra.w;
    }
    Bs[0][bkq + 0][brow] = rb.x; Bs[0][bkq + 1][brow] = rb.y;
    Bs[0][bkq + 2][brow] = rb.z; Bs[0][bkq + 3][brow] = rb.w;
    __syncthreads();

    const int T = DD / BK;  // 32 k-tiles
#pragma unroll 1
    for (int t = 0; t < T; t++) {
        const int cur = t & 1;
        const int nxt = cur ^ 1;

        // Prefetch next k-tile into registers (latency under compute)
        if (t + 1 < T) {
            if (aload) ra = *(const float4*)(gA + (t + 1) * BK);
            rb = *(const float4*)(gB + (t + 1) * BK);
        }

#pragma unroll
        for (int kk = 0; kk < BK; kk++) {
            const float2 av = *(const float2*)&As[cur][kk][tr * 2];
            const float4 bv = *(const float4*)&Bs[cur][kk][tc * 4];
            const float ar[2] = {av.x, av.y};
            const float br[4] = {bv.x, bv.y, bv.z, bv.w};
#pragma unroll
            for (int i = 0; i < 2; i++)
#pragma unroll
                for (int j = 0; j < 4; j++) acc[i][j] = fmaf(ar[i], br[j], acc[i][j]);
        }

        if (t + 1 < T) {
            if (aload) {
                As[nxt][akq + 0][arow] = ra.x; As[nxt][akq + 1][arow] = ra.y;
                As[nxt][akq + 2][arow] = ra.z; As[nxt][akq + 3][arow] = ra.w;
            }
            Bs[nxt][bkq + 0][brow] = rb.x; Bs[nxt][bkq + 1][brow] = rb.y;
            Bs[nxt][bkq + 2][brow] = rb.z; Bs[nxt][bkq + 3][brow] = rb.w;
        }
        __syncthreads();
    }

    // Epilogue: bias + sigmoid for i/f/o, write to scratch
    const bool gate = (which >= 3);
    const float* __restrict__ bias = gate ? a.bias[which - 3] : nullptr;
#pragma unroll
    for (int i = 0; i < 2; i++) {
        const int r = row0 + tr * 2 + i;
#pragma unroll
        for (int j = 0; j < 4; j++) {
            const int h = h0 + tc * 4 + j;
            float v = acc[i][j];
            if (gate) {
                v += bias[h];
                v = 1.0f / (1.0f + __expf(-v));
            }
            g_proj[which][r][h] = v;
        }
    }
}

// Fused state update + readout — R1 form, measured 78.6us @ 79% DRAM.
// Interleaved load->fma->store (MLP_p1 ~1) is deliberate: front-batched LDGs
// increase cross-CTA L1tex-queue spread on B300 and REGRESS this kernel.
// One warp per (b, i) row; block = 16 warps; grid (H/16, B).
__global__ __launch_bounds__(512) void update_kernel(const float* __restrict__ Cprev,
                                                     float* __restrict__ out_h,
                                                     float* __restrict__ out_C) {
    __shared__ float sv[HH];
    __shared__ float sq[HH];

    const int b   = blockIdx.y;
    const int i0  = blockIdx.x * 16;
    const int tid = threadIdx.x;

    // Stage v[b,:] and q[b,:] (shared across all 16 rows of this block)
    sv[tid] = g_proj[2][b][tid];
    sq[tid] = g_proj[0][b][tid];
    __syncthreads();

    const int warp = tid >> 5;
    const int lane = tid & 31;
    const int i    = i0 + warp;

    const float f_bi = g_proj[4][b][i];
    const float ik   = g_proj[3][b][i] * g_proj[1][b][i];
    const float o_bi = g_proj[5][b][i];

    const size_t rowoff = ((size_t)b * HH + i) * HH;
    const float4* __restrict__ Cp = (const float4*)(Cprev + rowoff);
    float4* __restrict__ Ct       = (float4*)(out_C + rowoff);
    const float4* __restrict__ v4 = (const float4*)sv;
    const float4* __restrict__ q4 = (const float4*)sq;

    float acc = 0.0f;
#pragma unroll
    for (int it = 0; it < 4; it++) {
        const int j4 = it * 32 + lane;    // 128 float4s per row
        float4 c = Cp[j4];
        const float4 vv = v4[j4];
        const float4 qq = q4[j4];
        c.x = fmaf(f_bi, c.x, ik * vv.x);
        c.y = fmaf(f_bi, c.y, ik * vv.y);
        c.z = fmaf(f_bi, c.z, ik * vv.z);
        c.w = fmaf(f_bi, c.w, ik * vv.w);
        Ct[j4] = c;
        acc += c.x * qq.x + c.y * qq.y + c.z * qq.z + c.w * qq.w;
    }

    // Warp reduction for the dot product
#pragma unroll
    for (int off = 16; off > 0; off >>= 1)
        acc += __shfl_xor_sync(0xFFFFFFFFu, acc, off);

    if (lane == 0) out_h[(size_t)b * HH + i] = o_bi * tanhf(acc);
}

extern "C" void kernel_launch(void* const* d_in, const int* in_sizes, int n_in,
                              void* d_out, int out_size) {
    // Inputs: 0:x 1:h_prev(unused) 2:C_prev 3:W_q 4:W_k 5:W_v 6:W_i 7:W_f 8:W_o 9:b_i 10:b_f 11:b_o
    const float* x     = (const float*)d_in[0];
    const float* Cprev = (const float*)d_in[2];

    GemmArgs a;
    a.x = x;
    a.W[0] = (const float*)d_in[3];
    a.W[1] = (const float*)d_in[4];
    a.W[2] = (const float*)d_in[5];
    a.W[3] = (const float*)d_in[6];
    a.W[4] = (const float*)d_in[7];
    a.W[5] = (const float*)d_in[8];
    a.bias[0] = (const float*)d_in[9];
    a.bias[1] = (const float*)d_in[10];
    a.bias[2] = (const float*)d_in[11];

    float* out = (float*)d_out;
    float* out_h = out;                       // [B, H]
    float* out_C = out + (size_t)BB * HH;     // [B, H, H]

    dim3 gGemm(48, 8);            // 384 blocks: 32x64 tiles, ~1 packed wave
    proj_kernel<<<gGemm, 256>>>(a);

    dim3 gUpd(HH / 16, BB);       // (32, 256) blocks, 512 threads
    update_kernel<<<gUpd, 512>>>(Cprev, out_h, out_C);
}